// round 1
// baseline (speedup 1.0000x reference)
#include <cuda_runtime.h>
#include <cuda_bf16.h>

// Sizes (fixed by the problem)
#define BB 4
#define NN 8192
#define CC 1024
#define SS 16
#define NTOK (BB * NN)       // 32768
#define CHUNK 64
#define NCHUNK (NN / CHUNK)  // 128 per batch

// Scratch: per-token state (pre-cumsum) [token][16], 2 MB -> L2 resident.
__device__ float g_xstate[NTOK * SS];
// Exclusive per-chunk prefixes [b][chunk][16]
__device__ float g_cprefix[BB * NCHUNK * SS];

// ---------- packed f32x2 helpers (sm_103a) ----------
__device__ __forceinline__ unsigned long long dup2(float x) {
    unsigned long long r;
    unsigned u = __float_as_uint(x);
    asm("mov.b64 %0, {%1, %1};" : "=l"(r) : "r"(u));
    return r;
}
__device__ __forceinline__ void fma2(unsigned long long& d, unsigned long long a,
                                     unsigned long long b) {
    asm("fma.rn.f32x2 %0, %1, %2, %0;" : "+l"(d) : "l"(a), "l"(b));
}
__device__ __forceinline__ unsigned long long add2(unsigned long long a,
                                                   unsigned long long b) {
    unsigned long long r;
    asm("add.rn.f32x2 %0, %1, %2;" : "=l"(r) : "l"(a), "l"(b));
    return r;
}

// ================= K1: x_state[t][j] = sum_c x[t][c] * A[c][j] =================
// Block = 256 thr = 8 warps, each warp handles 4 tokens.
// Lane owns c = c0 + lane + 32*i  (coalesced 128B gmem loads; smem A reads are
// LDS.64 at byte stride 8 per lane -> exactly 2 phases = minimum).
// A staged to smem as float2 A_t[jp][c]  (jp = j/2), 64 KB dynamic smem.
__global__ void __launch_bounds__(256) k1_xstate(const float* __restrict__ x,
                                                 const float* __restrict__ A) {
    extern __shared__ float2 As[];  // [8][1024]: As[jp*1024 + c]

    // Stage A (coalesced: consecutive threads read consecutive jp within a c-row)
    for (int idx = threadIdx.x; idx < 8 * CC; idx += 256) {
        int c = idx >> 3, jp = idx & 7;
        As[jp * CC + c] = *reinterpret_cast<const float2*>(A + c * SS + jp * 2);
    }
    __syncthreads();

    const int w = threadIdx.x >> 5;
    const int l = threadIdx.x & 31;
    const long t0 = (long)blockIdx.x * 32 + w * 4;
    const float* xp = x + t0 * CC;

    unsigned long long acc[4][8];
#pragma unroll
    for (int t = 0; t < 4; t++)
#pragma unroll
        for (int jp = 0; jp < 8; jp++) acc[t][jp] = 0ull;

#pragma unroll
    for (int p = 0; p < 8; p++) {
        const int c0 = p * 128;
        float xv[4][4];
#pragma unroll
        for (int t = 0; t < 4; t++)
#pragma unroll
            for (int i = 0; i < 4; i++)
                xv[t][i] = xp[t * CC + c0 + l + 32 * i];

#pragma unroll
        for (int i = 0; i < 4; i++) {
            const int c = c0 + l + 32 * i;
            unsigned long long xd[4];
#pragma unroll
            for (int t = 0; t < 4; t++) xd[t] = dup2(xv[t][i]);
#pragma unroll
            for (int jp = 0; jp < 8; jp++) {
                unsigned long long a2 =
                    *reinterpret_cast<const unsigned long long*>(&As[jp * CC + c]);
#pragma unroll
                for (int t = 0; t < 4; t++) fma2(acc[t][jp], xd[t], a2);
            }
        }
    }

    // Butterfly reduce each (t, jp) pair across the 32 lanes
#pragma unroll
    for (int ofs = 16; ofs; ofs >>= 1) {
#pragma unroll
        for (int t = 0; t < 4; t++)
#pragma unroll
            for (int jp = 0; jp < 8; jp++)
                acc[t][jp] = add2(acc[t][jp],
                                  __shfl_xor_sync(0xffffffffu, acc[t][jp], ofs));
    }

    // Lane l writes (t = l>>3, jp = l&7): warp writes 256B contiguous.
    const int t = l >> 3, jp = l & 7;
    *reinterpret_cast<unsigned long long*>(&g_xstate[(t0 + t) * SS + jp * 2]) =
        acc[t][jp];
}

// ================= K2: exclusive scan of chunk sums =================
// Grid = B*S = 64 blocks; 128 threads = one per chunk.
__global__ void __launch_bounds__(128) k2_scan() {
    const int b = blockIdx.x >> 4;
    const int j = blockIdx.x & 15;
    const int ch = threadIdx.x;  // 0..127

    const float* p = g_xstate + ((long)b * NN + (long)ch * CHUNK) * SS + j;
    float sum = 0.f;
#pragma unroll 8
    for (int i = 0; i < CHUNK; i++) sum += p[i * SS];

    __shared__ float sc[NCHUNK];
    sc[ch] = sum;
    __syncthreads();
    float v = sum;
    for (int o = 1; o < NCHUNK; o <<= 1) {
        float u = (ch >= o) ? sc[ch - o] : 0.f;
        __syncthreads();
        v += u;
        sc[ch] = v;
        __syncthreads();
    }
    g_cprefix[((long)b * NCHUNK + ch) * SS + j] = v - sum;  // exclusive
}

// ================= K3: local cumsum + (cumstate @ D) =================
// Grid = B*NCHUNK = 512 blocks of 256 thr. Block = one 64-token chunk.
__global__ void __launch_bounds__(256) k3_out(const float* __restrict__ Dg,
                                              float* __restrict__ out) {
    __shared__ float2 cs2[CHUNK][SS + 1];  // duplicated cumstate, padded rows

    const int b = blockIdx.x >> 7;
    const int ch = blockIdx.x & 127;
    const long T0 = (long)b * NN + (long)ch * CHUNK;
    const int w = threadIdx.x >> 5;
    const int l = threadIdx.x & 31;

    // Warp w computes the cumsum for j = 2w, 2w+1 via warp scans.
#pragma unroll
    for (int jj = 0; jj < 2; jj++) {
        const int j = w * 2 + jj;
        const float pfx = g_cprefix[((long)b * NCHUNK + ch) * SS + j];
        float v0 = g_xstate[(T0 + l) * SS + j];
        float v1 = g_xstate[(T0 + 32 + l) * SS + j];
#pragma unroll
        for (int o = 1; o < 32; o <<= 1) {
            float u = __shfl_up_sync(0xffffffffu, v0, o);
            if (l >= o) v0 += u;
        }
        const float carry = __shfl_sync(0xffffffffu, v0, 31);
#pragma unroll
        for (int o = 1; o < 32; o <<= 1) {
            float u = __shfl_up_sync(0xffffffffu, v1, o);
            if (l >= o) v1 += u;
        }
        v0 += pfx;
        v1 += pfx + carry;
        cs2[l][j] = make_float2(v0, v0);
        cs2[32 + l][j] = make_float2(v1, v1);
    }
    __syncthreads();

    // D fragment in registers: lane owns c = w*128 + 4*l + {0..3} (2 f32x2 pairs)
    const int cbase = w * 128 + l * 4;
    unsigned long long dfrag[SS][2];
#pragma unroll
    for (int j = 0; j < SS; j++) {
#pragma unroll
        for (int s = 0; s < 2; s++)
            dfrag[j][s] = *reinterpret_cast<const unsigned long long*>(
                Dg + j * CC + cbase + 2 * s);
    }

    float* op = out + T0 * CC + cbase;
#pragma unroll
    for (int tg = 0; tg < 16; tg++) {
#pragma unroll
        for (int t = 0; t < 4; t++) {
            const int tt = tg * 4 + t;
            unsigned long long o0 = 0ull, o1 = 0ull;
#pragma unroll
            for (int j = 0; j < SS; j++) {
                unsigned long long csd =
                    *reinterpret_cast<const unsigned long long*>(&cs2[tt][j]);
                fma2(o0, csd, dfrag[j][0]);
                fma2(o1, csd, dfrag[j][1]);
            }
            *reinterpret_cast<unsigned long long*>(op + (long)tt * CC) = o0;
            *reinterpret_cast<unsigned long long*>(op + (long)tt * CC + 2) = o1;
        }
    }
}

extern "C" void kernel_launch(void* const* d_in, const int* in_sizes, int n_in,
                              void* d_out, int out_size) {
    const float* x = (const float*)d_in[0];
    const float* A = (const float*)d_in[1];
    const float* D = (const float*)d_in[2];
    float* out = (float*)d_out;

    // 64 KB dynamic smem for K1's A tile (idempotent; not a stream op)
    cudaFuncSetAttribute(k1_xstate, cudaFuncAttributeMaxDynamicSharedMemorySize,
                         8 * CC * (int)sizeof(float2));

    k1_xstate<<<NTOK / 32, 256, 8 * CC * sizeof(float2)>>>(x, A);
    k2_scan<<<BB * SS, NCHUNK>>>();
    k3_out<<<BB * NCHUNK, 256>>>(D, out);
}